// round 1
// baseline (speedup 1.0000x reference)
#include <cuda_runtime.h>
#include <math.h>
#include <stdint.h>

#define BATCH 2
#define TT    2048
#define BT    (BATCH*TT)          // 4096
#define CC    512
#define HH    8
#define HDIM  64
#define LLAY  4
#define VV    50257
#define FFD   2048
#define LNEPS 1e-5f

// ---------------- scratch (static device memory; no allocs allowed) ----------
__device__ float g_h   [BT*CC];                 // residual stream
__device__ float g_ain [BT*CC];                 // layernorm output
__device__ float g_qkv [BT*3*CC];               // q|k|v packed per token
__device__ float g_attn[BT*CC];                 // attention output (concat heads)
__device__ float g_ff  [(size_t)BT*FFD];        // ff1 activation
__device__ float g_wqkv[(size_t)LLAY*CC*3*CC];  // packed qkv weights [l][c][3C]
__device__ float g_loss;

// ---------------- helpers ----------------------------------------------------
__device__ __forceinline__ float warpMax(float v) {
    #pragma unroll
    for (int o = 16; o; o >>= 1) v = fmaxf(v, __shfl_xor_sync(0xffffffffu, v, o));
    return v;
}
__device__ __forceinline__ float warpSum(float v) {
    #pragma unroll
    for (int o = 16; o; o >>= 1) v += __shfl_xor_sync(0xffffffffu, v, o);
    return v;
}

// ---------------- weight packing: [L,H,C,HD] x3 -> [L, C, 3C] ----------------
__global__ void pack_qkv_kernel(const float* __restrict__ wq,
                                const float* __restrict__ wk,
                                const float* __restrict__ wv) {
    int i = blockIdx.x * blockDim.x + threadIdx.x;
    const int total = LLAY * CC * 3 * CC;
    if (i >= total) return;
    int j = i % (3 * CC);
    int c = (i / (3 * CC)) % CC;
    int l = i / (3 * CC * CC);
    int which = j / CC;          // 0:q 1:k 2:v
    int jj = j % CC;
    int h = jj / HDIM, d = jj % HDIM;
    const float* w = (which == 0) ? wq : (which == 1) ? wk : wv;
    g_wqkv[i] = w[(((size_t)l * HH + h) * CC + c) * HDIM + d];
}

// ---------------- embedding ---------------------------------------------------
__global__ void embed_kernel(const int* __restrict__ x,
                             const float* __restrict__ tok,
                             const float* __restrict__ pos) {
    int i = blockIdx.x * blockDim.x + threadIdx.x;
    if (i >= BT * CC) return;
    int c  = i % CC;
    int bt = i / CC;
    int t  = bt % TT;
    g_h[i] = tok[(size_t)x[bt] * CC + c] + pos[(size_t)t * CC + c];
}

// ---------------- layernorm: one block per row (C=512, 256 threads) ----------
__global__ void ln_kernel(const float* __restrict__ in,
                          const float* __restrict__ sc,
                          const float* __restrict__ bi,
                          float* __restrict__ out) {
    int row = blockIdx.x, tid = threadIdx.x;
    const float* r = in + (size_t)row * CC;
    float a = r[tid], b = r[tid + 256];
    float s = a + b, q = a * a + b * b;
    s = warpSum(s); q = warpSum(q);
    __shared__ float rs[8], rq[8];
    if ((tid & 31) == 0) { rs[tid >> 5] = s; rq[tid >> 5] = q; }
    __syncthreads();
    __shared__ float s_mean, s_rstd;
    if (tid == 0) {
        float S = 0.f, Q = 0.f;
        #pragma unroll
        for (int i = 0; i < 8; i++) { S += rs[i]; Q += rq[i]; }
        float m = S * (1.0f / CC);
        float v = Q * (1.0f / CC) - m * m;
        s_mean = m; s_rstd = rsqrtf(v + LNEPS);
    }
    __syncthreads();
    float m = s_mean, rstd = s_rstd;
    float* o = out + (size_t)row * CC;
    o[tid]       = (a - m) * rstd * sc[tid]       + bi[tid];
    o[tid + 256] = (b - m) * rstd * sc[tid + 256] + bi[tid + 256];
}

// ---------------- generic fp32 GEMM: C = A[M,K] @ B[K,N] (+bias,+res,relu) ---
// 64x64 tile, BK=16, 256 threads, 4x4 per thread. K must be multiple of 16.
__global__ void gemm_kernel(const float* __restrict__ A,
                            const float* __restrict__ B,
                            float* __restrict__ Cout,
                            int M, int N, int K,
                            const float* __restrict__ bias,
                            const float* __restrict__ res,
                            int relu) {
    __shared__ float As[16][65];
    __shared__ float Bs[16][65];
    int tid = threadIdx.x;
    int tx = tid & 15, ty = tid >> 4;
    int row0 = blockIdx.y * 64, col0 = blockIdx.x * 64;
    float acc[4][4] = {};

    for (int k0 = 0; k0 < K; k0 += 16) {
        #pragma unroll
        for (int i = 0; i < 4; i++) {
            int idx = tid + i * 256;
            int r = idx >> 4, c = idx & 15;
            int gr = row0 + r;
            As[c][r] = (gr < M) ? A[(size_t)gr * K + k0 + c] : 0.f;
        }
        #pragma unroll
        for (int i = 0; i < 4; i++) {
            int idx = tid + i * 256;
            int r = idx >> 6, c = idx & 63;
            int gc = col0 + c;
            Bs[r][c] = (gc < N) ? B[(size_t)(k0 + r) * N + gc] : 0.f;
        }
        __syncthreads();
        #pragma unroll
        for (int k = 0; k < 16; k++) {
            float ra[4], rb[4];
            #pragma unroll
            for (int i = 0; i < 4; i++) ra[i] = As[k][ty * 4 + i];
            #pragma unroll
            for (int j = 0; j < 4; j++) rb[j] = Bs[k][tx * 4 + j];
            #pragma unroll
            for (int i = 0; i < 4; i++)
                #pragma unroll
                for (int j = 0; j < 4; j++)
                    acc[i][j] = fmaf(ra[i], rb[j], acc[i][j]);
        }
        __syncthreads();
    }

    #pragma unroll
    for (int i = 0; i < 4; i++) {
        int r = row0 + ty * 4 + i;
        if (r >= M) continue;
        #pragma unroll
        for (int j = 0; j < 4; j++) {
            int c = col0 + tx * 4 + j;
            if (c >= N) continue;
            float v = acc[i][j];
            if (bias) v += bias[c];
            if (res)  v += res[(size_t)r * N + c];
            if (relu) v = fmaxf(v, 0.f);
            Cout[(size_t)r * N + c] = v;
        }
    }
}

// ---------------- causal attention: one block per (b,h,t), 128 threads -------
__global__ void attn_kernel(const float* __restrict__ qkv,
                            float* __restrict__ out) {
    __shared__ float scb[TT];
    __shared__ float qs[HDIM];
    __shared__ float red[4];
    __shared__ float comb[128];
    int bid = blockIdx.x;
    int t = bid % TT;
    int h = (bid / TT) % HH;
    int b = bid / (TT * HH);
    int tid = threadIdx.x;

    const size_t rowQ = ((size_t)(b * TT + t)) * (3 * CC) + h * HDIM;
    if (tid < HDIM) qs[tid] = qkv[rowQ + tid];
    __syncthreads();

    int nS = t + 1;
    float mx = -1e30f;
    for (int s = tid; s < nS; s += 128) {
        const float* kr = qkv + ((size_t)(b * TT + s)) * (3 * CC) + CC + h * HDIM;
        float d = 0.f;
        #pragma unroll
        for (int k = 0; k < HDIM; k++) d = fmaf(qs[k], kr[k], d);
        d *= 0.125f;   // 1/sqrt(64)
        scb[s] = d;
        mx = fmaxf(mx, d);
    }
    mx = warpMax(mx);
    if ((tid & 31) == 0) red[tid >> 5] = mx;
    __syncthreads();
    mx = fmaxf(fmaxf(red[0], red[1]), fmaxf(red[2], red[3]));
    __syncthreads();

    float sm = 0.f;
    for (int s = tid; s < nS; s += 128) {
        float e = __expf(scb[s] - mx);
        scb[s] = e;
        sm += e;
    }
    sm = warpSum(sm);
    if ((tid & 31) == 0) red[tid >> 5] = sm;
    __syncthreads();
    sm = red[0] + red[1] + red[2] + red[3];
    float inv = 1.f / sm;

    int d = tid & 63, part = tid >> 6;
    float acc = 0.f;
    for (int s = part; s < nS; s += 2) {
        const float* vr = qkv + ((size_t)(b * TT + s)) * (3 * CC) + 2 * CC + h * HDIM;
        acc = fmaf(scb[s], vr[d], acc);
    }
    comb[tid] = acc;
    __syncthreads();
    if (tid < 64)
        out[((size_t)(b * TT + t)) * CC + h * HDIM + tid] =
            (comb[tid] + comb[tid + 64]) * inv;
}

// ---------------- loss: per-row logsumexp over V ------------------------------
__global__ void zero_loss_kernel() { g_loss = 0.f; }

__global__ void loss_kernel(const float* __restrict__ logits,
                            const int* __restrict__ target) {
    int row = blockIdx.x, tid = threadIdx.x;   // 256 threads
    const float* lr = logits + (size_t)row * VV;
    float mx = -1e30f;
    for (int i = tid; i < VV; i += 256) mx = fmaxf(mx, lr[i]);
    __shared__ float red[8];
    mx = warpMax(mx);
    if ((tid & 31) == 0) red[tid >> 5] = mx;
    __syncthreads();
    float m = red[0];
    #pragma unroll
    for (int i = 1; i < 8; i++) m = fmaxf(m, red[i]);
    __syncthreads();

    float sm = 0.f;
    for (int i = tid; i < VV; i += 256) sm += expf(lr[i] - m);
    sm = warpSum(sm);
    if ((tid & 31) == 0) red[tid >> 5] = sm;
    __syncthreads();
    if (tid == 0) {
        float S = 0.f;
        #pragma unroll
        for (int i = 0; i < 8; i++) S += red[i];
        float lse = m + logf(S);
        atomicAdd(&g_loss, lse - lr[target[row]]);
    }
}

__global__ void finalize_loss_kernel(float* __restrict__ out) {
    out[(size_t)BT * VV] = g_loss * (1.0f / BT);
}

// ---------------- launch ------------------------------------------------------
extern "C" void kernel_launch(void* const* d_in, const int* in_sizes, int n_in,
                              void* d_out, int out_size) {
    const int*   x      = (const int*)  d_in[0];
    const int*   target = (const int*)  d_in[1];
    const float* tok    = (const float*)d_in[2];
    const float* pos    = (const float*)d_in[3];
    const float* ln1s   = (const float*)d_in[4];
    const float* ln1b   = (const float*)d_in[5];
    const float* wq     = (const float*)d_in[6];
    const float* wk     = (const float*)d_in[7];
    const float* wv     = (const float*)d_in[8];
    const float* wproj  = (const float*)d_in[9];
    const float* bproj  = (const float*)d_in[10];
    const float* ln2s   = (const float*)d_in[11];
    const float* ln2b   = (const float*)d_in[12];
    const float* wff1   = (const float*)d_in[13];
    const float* bff1   = (const float*)d_in[14];
    const float* wff2   = (const float*)d_in[15];
    const float* bff2   = (const float*)d_in[16];
    const float* lnfs   = (const float*)d_in[17];
    const float* lnfb   = (const float*)d_in[18];
    const float* lmw    = (const float*)d_in[19];
    const float* lmb    = (const float*)d_in[20];
    float* out = (float*)d_out;

    float *p_h, *p_ain, *p_qkv, *p_attn, *p_ff, *p_wqkv;
    cudaGetSymbolAddress((void**)&p_h,    g_h);
    cudaGetSymbolAddress((void**)&p_ain,  g_ain);
    cudaGetSymbolAddress((void**)&p_qkv,  g_qkv);
    cudaGetSymbolAddress((void**)&p_attn, g_attn);
    cudaGetSymbolAddress((void**)&p_ff,   g_ff);
    cudaGetSymbolAddress((void**)&p_wqkv, g_wqkv);

    const int packN = LLAY * CC * 3 * CC;
    pack_qkv_kernel<<<(packN + 255) / 256, 256>>>(wq, wk, wv);
    embed_kernel<<<(BT * CC + 255) / 256, 256>>>(x, tok, pos);

    dim3 gQKV((3 * CC + 63) / 64, BT / 64);
    dim3 gC  ((CC + 63) / 64,     BT / 64);
    dim3 gFF ((FFD + 63) / 64,    BT / 64);
    dim3 gV  ((VV + 63) / 64,     BT / 64);

    for (int l = 0; l < LLAY; l++) {
        ln_kernel<<<BT, 256>>>(p_h, ln1s + l * CC, ln1b + l * CC, p_ain);
        gemm_kernel<<<gQKV, 256>>>(p_ain, p_wqkv + (size_t)l * CC * 3 * CC, p_qkv,
                                   BT, 3 * CC, CC, nullptr, nullptr, 0);
        attn_kernel<<<BATCH * HH * TT, 128>>>(p_qkv, p_attn);
        gemm_kernel<<<gC, 256>>>(p_attn, wproj + (size_t)l * CC * CC, p_h,
                                 BT, CC, CC, bproj + l * CC, p_h, 0);
        ln_kernel<<<BT, 256>>>(p_h, ln2s + l * CC, ln2b + l * CC, p_ain);
        gemm_kernel<<<gFF, 256>>>(p_ain, wff1 + (size_t)l * CC * FFD, p_ff,
                                  BT, FFD, CC, bff1 + l * FFD, nullptr, 1);
        gemm_kernel<<<gC, 256>>>(p_ff, wff2 + (size_t)l * FFD * CC, p_h,
                                 BT, CC, FFD, bff2 + l * CC, p_h, 0);
    }

    ln_kernel<<<BT, 256>>>(p_h, lnfs, lnfb, p_ain);
    gemm_kernel<<<gV, 256>>>(p_ain, lmw, out, BT, VV, CC, lmb, nullptr, 0);

    if ((long long)out_size > (long long)BT * VV) {
        zero_loss_kernel<<<1, 1>>>();
        loss_kernel<<<BT, 256>>>(out, target);
        finalize_loss_kernel<<<1, 1>>>(out);
    }
}

// round 2
// speedup vs baseline: 5.8766x; 5.8766x over previous
#include <cuda_runtime.h>
#include <math.h>
#include <stdint.h>

#define BATCH 2
#define TT    2048
#define BT    (BATCH*TT)          // 4096
#define CC    512
#define HH    8
#define HDIM  64
#define LLAY  4
#define VV    50257
#define FFD   2048
#define LNEPS 1e-5f
#define BHZ   (BATCH*HH)          // 16

// ---------------- scratch (static device memory) -----------------------------
__device__ float g_h   [BT*CC];
__device__ float g_ain [BT*CC];
__device__ float g_qkv [BT*3*CC];
__device__ float g_attn[BT*CC];
__device__ float g_ff  [(size_t)BT*FFD];
__device__ float g_wqkv[(size_t)LLAY*CC*3*CC];
__device__ float g_scores[(size_t)BHZ*TT*TT];       // 268 MB score/prob buffer
__device__ float g_loss;

// ---------------- helpers ----------------------------------------------------
__device__ __forceinline__ float warpMax(float v) {
    #pragma unroll
    for (int o = 16; o; o >>= 1) v = fmaxf(v, __shfl_xor_sync(0xffffffffu, v, o));
    return v;
}
__device__ __forceinline__ float warpSum(float v) {
    #pragma unroll
    for (int o = 16; o; o >>= 1) v += __shfl_xor_sync(0xffffffffu, v, o);
    return v;
}
__device__ __forceinline__ float tf32r(float x) {
    uint32_t u;
    asm("cvt.rna.tf32.f32 %0, %1;" : "=r"(u) : "f"(x));
    return __uint_as_float(u);
}
__device__ __forceinline__ void mma8(float* c, const uint32_t* a, const uint32_t* b) {
    asm volatile(
        "mma.sync.aligned.m16n8k8.row.col.f32.tf32.tf32.f32 "
        "{%0,%1,%2,%3}, {%4,%5,%6,%7}, {%8,%9}, {%0,%1,%2,%3};"
        : "+f"(c[0]), "+f"(c[1]), "+f"(c[2]), "+f"(c[3])
        : "r"(a[0]), "r"(a[1]), "r"(a[2]), "r"(a[3]), "r"(b[0]), "r"(b[1]));
}

// ---------------- weight packing: [L,H,C,HD] x3 -> [L, C, 3C] ----------------
__global__ void pack_qkv_kernel(const float* __restrict__ wq,
                                const float* __restrict__ wk,
                                const float* __restrict__ wv) {
    int i = blockIdx.x * blockDim.x + threadIdx.x;
    const int total = LLAY * CC * 3 * CC;
    if (i >= total) return;
    int j = i % (3 * CC);
    int c = (i / (3 * CC)) % CC;
    int l = i / (3 * CC * CC);
    int which = j / CC;
    int jj = j % CC;
    int h = jj / HDIM, d = jj % HDIM;
    const float* w = (which == 0) ? wq : (which == 1) ? wk : wv;
    g_wqkv[i] = w[(((size_t)l * HH + h) * CC + c) * HDIM + d];
}

// ---------------- embedding ---------------------------------------------------
__global__ void embed_kernel(const int* __restrict__ x,
                             const float* __restrict__ tok,
                             const float* __restrict__ pos) {
    int i = blockIdx.x * blockDim.x + threadIdx.x;
    if (i >= BT * CC) return;
    int c  = i % CC;
    int bt = i / CC;
    int t  = bt % TT;
    g_h[i] = tok[(size_t)x[bt] * CC + c] + pos[(size_t)t * CC + c];
}

// ---------------- layernorm ---------------------------------------------------
__global__ void ln_kernel(const float* __restrict__ in,
                          const float* __restrict__ sc,
                          const float* __restrict__ bi,
                          float* __restrict__ out) {
    int row = blockIdx.x, tid = threadIdx.x;
    const float* r = in + (size_t)row * CC;
    float a = r[tid], b = r[tid + 256];
    float s = a + b, q = a * a + b * b;
    s = warpSum(s); q = warpSum(q);
    __shared__ float rs[8], rq[8];
    if ((tid & 31) == 0) { rs[tid >> 5] = s; rq[tid >> 5] = q; }
    __syncthreads();
    __shared__ float s_mean, s_rstd;
    if (tid == 0) {
        float S = 0.f, Q = 0.f;
        #pragma unroll
        for (int i = 0; i < 8; i++) { S += rs[i]; Q += rq[i]; }
        float m = S * (1.0f / CC);
        float v = Q * (1.0f / CC) - m * m;
        s_mean = m; s_rstd = rsqrtf(v + LNEPS);
    }
    __syncthreads();
    float m = s_mean, rstd = s_rstd;
    float* o = out + (size_t)row * CC;
    o[tid]       = (a - m) * rstd * sc[tid]       + bi[tid];
    o[tid + 256] = (b - m) * rstd * sc[tid + 256] + bi[tid + 256];
}

// ---------------- tf32 tensor-core GEMM: C = A[M,K] @ B[K,N] -----------------
// 128x64 block tile, BK=16, 256 threads (8 warps: 4 row x 2 col, 32x32 each).
__global__ void gemm_tf32_kernel(const float* __restrict__ A,
                                 const float* __restrict__ B,
                                 float* __restrict__ Cout,
                                 int M, int N, int K,
                                 const float* __restrict__ bias,
                                 const float* __restrict__ res,
                                 int relu) {
    __shared__ float As[16][136];   // [k][m], pad 136 (%32==8): frag reads conflict-free
    __shared__ float Bs[16][72];    // [k][n], pad 72  (%32==8)
    int tid = threadIdx.x;
    int lane = tid & 31, gid = lane >> 2, tig = lane & 3;
    int wid = tid >> 5;
    int wr = (wid >> 1) * 32;
    int wc = (wid & 1) * 32;
    int row0 = blockIdx.y * 128, col0 = blockIdx.x * 64;
    bool nAligned = ((N & 63) == 0);

    float acc[2][4][4];
    #pragma unroll
    for (int i = 0; i < 2; i++)
        #pragma unroll
        for (int j = 0; j < 4; j++)
            #pragma unroll
            for (int q = 0; q < 4; q++) acc[i][j][q] = 0.f;

    for (int k0 = 0; k0 < K; k0 += 16) {
        // A tile: 128x16, float4 along k, transposed store
        #pragma unroll
        for (int i = 0; i < 2; i++) {
            int f4 = tid + i * 256;
            int r = f4 >> 2, kc = (f4 & 3) << 2;
            float4 v = *reinterpret_cast<const float4*>(
                A + (size_t)(row0 + r) * K + k0 + kc);
            As[kc + 0][r] = tf32r(v.x);
            As[kc + 1][r] = tf32r(v.y);
            As[kc + 2][r] = tf32r(v.z);
            As[kc + 3][r] = tf32r(v.w);
        }
        // B tile: 16x64, n-contiguous
        {
            int r = tid >> 4, c = (tid & 15) << 2;
            int gc = col0 + c;
            if (nAligned) {
                float4 v = *reinterpret_cast<const float4*>(
                    B + (size_t)(k0 + r) * N + gc);
                Bs[r][c + 0] = tf32r(v.x);
                Bs[r][c + 1] = tf32r(v.y);
                Bs[r][c + 2] = tf32r(v.z);
                Bs[r][c + 3] = tf32r(v.w);
            } else {
                const float* bp = B + (size_t)(k0 + r) * N;
                #pragma unroll
                for (int j = 0; j < 4; j++)
                    Bs[r][c + j] = (gc + j < N) ? tf32r(bp[gc + j]) : 0.f;
            }
        }
        __syncthreads();
        #pragma unroll
        for (int ks = 0; ks < 2; ks++) {
            int kb = ks * 8;
            uint32_t a[2][4], bb[4][2];
            #pragma unroll
            for (int i = 0; i < 2; i++) {
                int m = wr + i * 16 + gid;
                a[i][0] = __float_as_uint(As[kb + tig    ][m    ]);
                a[i][1] = __float_as_uint(As[kb + tig    ][m + 8]);
                a[i][2] = __float_as_uint(As[kb + tig + 4][m    ]);
                a[i][3] = __float_as_uint(As[kb + tig + 4][m + 8]);
            }
            #pragma unroll
            for (int j = 0; j < 4; j++) {
                int n = wc + j * 8 + gid;
                bb[j][0] = __float_as_uint(Bs[kb + tig    ][n]);
                bb[j][1] = __float_as_uint(Bs[kb + tig + 4][n]);
            }
            #pragma unroll
            for (int i = 0; i < 2; i++)
                #pragma unroll
                for (int j = 0; j < 4; j++)
                    mma8(acc[i][j], a[i], bb[j]);
        }
        __syncthreads();
    }

    #pragma unroll
    for (int i = 0; i < 2; i++)
        #pragma unroll
        for (int j = 0; j < 4; j++) {
            int c0 = col0 + wc + j * 8 + tig * 2;
            #pragma unroll
            for (int half = 0; half < 2; half++) {
                int r = row0 + wr + i * 16 + gid + half * 8;
                float v0 = acc[i][j][half * 2 + 0];
                float v1 = acc[i][j][half * 2 + 1];
                if (c0 < N) {
                    if (bias) v0 += bias[c0];
                    if (res)  v0 += res[(size_t)r * N + c0];
                    if (relu) v0 = fmaxf(v0, 0.f);
                    Cout[(size_t)r * N + c0] = v0;
                }
                if (c0 + 1 < N) {
                    if (bias) v1 += bias[c0 + 1];
                    if (res)  v1 += res[(size_t)r * N + c0 + 1];
                    if (relu) v1 = fmaxf(v1, 0.f);
                    Cout[(size_t)r * N + c0 + 1] = v1;
                }
            }
        }
}

// ---------------- QK^T: scores[z][t][s] = 0.125 * Q_t . K_s (causal-masked) --
// 64x64 tile per block, K=64. Upper-triangle blocks skipped.
__global__ void qk_kernel(const float* __restrict__ qkv,
                          float* __restrict__ scores) {
    __shared__ float Qs[64][72];   // [d][t]
    __shared__ float Ks[64][72];   // [d][s]
    int col0 = blockIdx.x * 64;    // s
    int row0 = blockIdx.y * 64;    // t
    if (col0 > row0 + 63) return;
    int z = blockIdx.z;
    int b = z >> 3, h = z & 7;
    const float* qbase = qkv + (size_t)b * TT * (3 * CC) + h * HDIM;
    const float* kbase = qbase + CC;
    int tid = threadIdx.x;

    #pragma unroll
    for (int i = 0; i < 4; i++) {
        int f4 = tid + i * 256;
        int r = f4 >> 4, kc = (f4 & 15) << 2;
        float4 q = *reinterpret_cast<const float4*>(
            qbase + (size_t)(row0 + r) * (3 * CC) + kc);
        float4 k = *reinterpret_cast<const float4*>(
            kbase + (size_t)(col0 + r) * (3 * CC) + kc);
        Qs[kc + 0][r] = tf32r(q.x); Qs[kc + 1][r] = tf32r(q.y);
        Qs[kc + 2][r] = tf32r(q.z); Qs[kc + 3][r] = tf32r(q.w);
        Ks[kc + 0][r] = tf32r(k.x); Ks[kc + 1][r] = tf32r(k.y);
        Ks[kc + 2][r] = tf32r(k.z); Ks[kc + 3][r] = tf32r(k.w);
    }
    __syncthreads();

    int lane = tid & 31, gid = lane >> 2, tig = lane & 3;
    int wid = tid >> 5;
    int wr = (wid >> 2) * 32, wc = (wid & 3) * 16;
    float acc[2][2][4] = {};

    #pragma unroll
    for (int ks = 0; ks < 8; ks++) {
        int kb = ks * 8;
        uint32_t a[2][4], bb[2][2];
        #pragma unroll
        for (int i = 0; i < 2; i++) {
            int m = wr + i * 16 + gid;
            a[i][0] = __float_as_uint(Qs[kb + tig    ][m    ]);
            a[i][1] = __float_as_uint(Qs[kb + tig    ][m + 8]);
            a[i][2] = __float_as_uint(Qs[kb + tig + 4][m    ]);
            a[i][3] = __float_as_uint(Qs[kb + tig + 4][m + 8]);
        }
        #pragma unroll
        for (int j = 0; j < 2; j++) {
            int n = wc + j * 8 + gid;
            bb[j][0] = __float_as_uint(Ks[kb + tig    ][n]);
            bb[j][1] = __float_as_uint(Ks[kb + tig + 4][n]);
        }
        #pragma unroll
        for (int i = 0; i < 2; i++)
            #pragma unroll
            for (int j = 0; j < 2; j++)
                mma8(acc[i][j], a[i], bb[j]);
    }

    #pragma unroll
    for (int i = 0; i < 2; i++)
        #pragma unroll
        for (int j = 0; j < 2; j++) {
            int s0 = col0 + wc + j * 8 + tig * 2;
            #pragma unroll
            for (int half = 0; half < 2; half++) {
                int t = row0 + wr + i * 16 + gid + half * 8;
                float v0 = acc[i][j][half * 2 + 0] * 0.125f;
                float v1 = acc[i][j][half * 2 + 1] * 0.125f;
                if (s0     > t) v0 = -1e30f;
                if (s0 + 1 > t) v1 = -1e30f;
                float* orow = scores + ((size_t)z * TT + t) * TT + s0;
                orow[0] = v0;
                orow[1] = v1;
            }
        }
}

// ---------------- softmax row (prefix [0..t], zero suffix), in-place ---------
__global__ void softmax_kernel(float* __restrict__ scores) {
    __shared__ float scb[TT];
    __shared__ float red[8];
    int bx = blockIdx.x;
    int z = bx >> 11, t = bx & (TT - 1);
    float* row = scores + ((size_t)z * TT + t) * TT;
    int n = t + 1, tid = threadIdx.x;

    float mx = -1e30f;
    for (int i = tid; i < n; i += 256) { float v = row[i]; scb[i] = v; mx = fmaxf(mx, v); }
    mx = warpMax(mx);
    if ((tid & 31) == 0) red[tid >> 5] = mx;
    __syncthreads();
    float m = red[0];
    #pragma unroll
    for (int i = 1; i < 8; i++) m = fmaxf(m, red[i]);
    __syncthreads();

    float sm = 0.f;
    for (int i = tid; i < n; i += 256) { float e = __expf(scb[i] - m); scb[i] = e; sm += e; }
    sm = warpSum(sm);
    if ((tid & 31) == 0) red[tid >> 5] = sm;
    __syncthreads();
    float S = 0.f;
    #pragma unroll
    for (int i = 0; i < 8; i++) S += red[i];
    float inv = 1.f / S;

    for (int i4 = tid; i4 < TT / 4; i4 += 256) {
        int i = i4 * 4;
        float4 o;
        o.x = (i     < n) ? scb[i    ] * inv : 0.f;
        o.y = (i + 1 < n) ? scb[i + 1] * inv : 0.f;
        o.z = (i + 2 < n) ? scb[i + 2] * inv : 0.f;
        o.w = (i + 3 < n) ? scb[i + 3] * inv : 0.f;
        *reinterpret_cast<float4*>(row + i) = o;
    }
}

// ---------------- PV: attn[t][d] = sum_s P[t][s] V[s][d] (causal-trimmed) ----
__global__ void pv_kernel(const float* __restrict__ probs,
                          const float* __restrict__ qkv,
                          float* __restrict__ outp) {
    __shared__ float As[32][72];   // [s][t] transposed P tile
    __shared__ float Bs[32][72];   // [s][d] V tile
    int row0 = blockIdx.x * 64;    // t tile
    int z = blockIdx.y;
    int b = z >> 3, h = z & 7;
    const float* pbase = probs + (size_t)z * TT * TT;
    const float* vbase = qkv + (size_t)b * TT * (3 * CC) + 2 * CC + h * HDIM;
    int tid = threadIdx.x;
    int lane = tid & 31, gid = lane >> 2, tig = lane & 3;
    int wid = tid >> 5;
    int wr = (wid >> 2) * 32, wc = (wid & 3) * 16;
    float acc[2][2][4] = {};

    int kend = row0 + 64;   // s > row0+63 contributes 0 to every t in tile
    for (int k0 = 0; k0 < kend; k0 += 32) {
        #pragma unroll
        for (int i = 0; i < 2; i++) {
            int f4 = tid + i * 256;
            int r = f4 >> 3, kc = (f4 & 7) << 2;
            float4 v = *reinterpret_cast<const float4*>(
                pbase + (size_t)(row0 + r) * TT + k0 + kc);
            As[kc + 0][r] = tf32r(v.x);
            As[kc + 1][r] = tf32r(v.y);
            As[kc + 2][r] = tf32r(v.z);
            As[kc + 3][r] = tf32r(v.w);
        }
        #pragma unroll
        for (int i = 0; i < 2; i++) {
            int f4 = tid + i * 256;
            int r = f4 >> 4, c = (f4 & 15) << 2;
            float4 v = *reinterpret_cast<const float4*>(
                vbase + (size_t)(k0 + r) * (3 * CC) + c);
            Bs[r][c + 0] = tf32r(v.x);
            Bs[r][c + 1] = tf32r(v.y);
            Bs[r][c + 2] = tf32r(v.z);
            Bs[r][c + 3] = tf32r(v.w);
        }
        __syncthreads();
        #pragma unroll
        for (int ks = 0; ks < 4; ks++) {
            int kb = ks * 8;
            uint32_t a[2][4], bb[2][2];
            #pragma unroll
            for (int i = 0; i < 2; i++) {
                int m = wr + i * 16 + gid;
                a[i][0] = __float_as_uint(As[kb + tig    ][m    ]);
                a[i][1] = __float_as_uint(As[kb + tig    ][m + 8]);
                a[i][2] = __float_as_uint(As[kb + tig + 4][m    ]);
                a[i][3] = __float_as_uint(As[kb + tig + 4][m + 8]);
            }
            #pragma unroll
            for (int j = 0; j < 2; j++) {
                int n = wc + j * 8 + gid;
                bb[j][0] = __float_as_uint(Bs[kb + tig    ][n]);
                bb[j][1] = __float_as_uint(Bs[kb + tig + 4][n]);
            }
            #pragma unroll
            for (int i = 0; i < 2; i++)
                #pragma unroll
                for (int j = 0; j < 2; j++)
                    mma8(acc[i][j], a[i], bb[j]);
        }
        __syncthreads();
    }

    #pragma unroll
    for (int i = 0; i < 2; i++)
        #pragma unroll
        for (int j = 0; j < 2; j++) {
            int d0 = wc + j * 8 + tig * 2;
            #pragma unroll
            for (int half = 0; half < 2; half++) {
                int t = row0 + wr + i * 16 + gid + half * 8;
                float* op = outp + ((size_t)(b * TT + t)) * CC + h * HDIM + d0;
                op[0] = acc[i][j][half * 2 + 0];
                op[1] = acc[i][j][half * 2 + 1];
            }
        }
}

// ---------------- loss --------------------------------------------------------
__global__ void zero_loss_kernel() { g_loss = 0.f; }

__global__ void loss_kernel(const float* __restrict__ logits,
                            const int* __restrict__ target) {
    int row = blockIdx.x, tid = threadIdx.x;
    const float* lr = logits + (size_t)row * VV;
    float mx = -1e30f;
    for (int i = tid; i < VV; i += 256) mx = fmaxf(mx, lr[i]);
    __shared__ float red[8];
    mx = warpMax(mx);
    if ((tid & 31) == 0) red[tid >> 5] = mx;
    __syncthreads();
    float m = red[0];
    #pragma unroll
    for (int i = 1; i < 8; i++) m = fmaxf(m, red[i]);
    __syncthreads();

    float sm = 0.f;
    for (int i = tid; i < VV; i += 256) sm += __expf(lr[i] - m);
    sm = warpSum(sm);
    if ((tid & 31) == 0) red[tid >> 5] = sm;
    __syncthreads();
    if (tid == 0) {
        float S = 0.f;
        #pragma unroll
        for (int i = 0; i < 8; i++) S += red[i];
        float lse = m + logf(S);
        atomicAdd(&g_loss, lse - lr[target[row]]);
    }
}

__global__ void finalize_loss_kernel(float* __restrict__ out) {
    out[(size_t)BT * VV] = g_loss * (1.0f / BT);
}

// ---------------- launch ------------------------------------------------------
extern "C" void kernel_launch(void* const* d_in, const int* in_sizes, int n_in,
                              void* d_out, int out_size) {
    const int*   x      = (const int*)  d_in[0];
    const int*   target = (const int*)  d_in[1];
    const float* tok    = (const float*)d_in[2];
    const float* pos    = (const float*)d_in[3];
    const float* ln1s   = (const float*)d_in[4];
    const float* ln1b   = (const float*)d_in[5];
    const float* wq     = (const float*)d_in[6];
    const float* wk     = (const float*)d_in[7];
    const float* wv     = (const float*)d_in[8];
    const float* wproj  = (const float*)d_in[9];
    const float* bproj  = (const float*)d_in[10];
    const float* ln2s   = (const float*)d_in[11];
    const float* ln2b   = (const float*)d_in[12];
    const float* wff1   = (const float*)d_in[13];
    const float* bff1   = (const float*)d_in[14];
    const float* wff2   = (const float*)d_in[15];
    const float* bff2   = (const float*)d_in[16];
    const float* lnfs   = (const float*)d_in[17];
    const float* lnfb   = (const float*)d_in[18];
    const float* lmw    = (const float*)d_in[19];
    const float* lmb    = (const float*)d_in[20];
    float* out = (float*)d_out;

    float *p_h, *p_ain, *p_qkv, *p_attn, *p_ff, *p_wqkv, *p_sc;
    cudaGetSymbolAddress((void**)&p_h,    g_h);
    cudaGetSymbolAddress((void**)&p_ain,  g_ain);
    cudaGetSymbolAddress((void**)&p_qkv,  g_qkv);
    cudaGetSymbolAddress((void**)&p_attn, g_attn);
    cudaGetSymbolAddress((void**)&p_ff,   g_ff);
    cudaGetSymbolAddress((void**)&p_wqkv, g_wqkv);
    cudaGetSymbolAddress((void**)&p_sc,   g_scores);

    const int packN = LLAY * CC * 3 * CC;
    pack_qkv_kernel<<<(packN + 255) / 256, 256>>>(wq, wk, wv);
    embed_kernel<<<(BT * CC + 255) / 256, 256>>>(x, tok, pos);

    dim3 gQKV((3 * CC) / 64, BT / 128);
    dim3 gC  (CC / 64,       BT / 128);
    dim3 gFF (FFD / 64,      BT / 128);
    dim3 gV  ((VV + 63) / 64, BT / 128);
    dim3 gQK (TT / 64, TT / 64, BHZ);
    dim3 gPV (TT / 64, BHZ);

    for (int l = 0; l < LLAY; l++) {
        ln_kernel<<<BT, 256>>>(p_h, ln1s + l * CC, ln1b + l * CC, p_ain);
        gemm_tf32_kernel<<<gQKV, 256>>>(p_ain, p_wqkv + (size_t)l * CC * 3 * CC,
                                        p_qkv, BT, 3 * CC, CC, nullptr, nullptr, 0);
        qk_kernel<<<gQK, 256>>>(p_qkv, p_sc);
        softmax_kernel<<<BHZ * TT, 256>>>(p_sc);
        pv_kernel<<<gPV, 256>>>(p_sc, p_qkv, p_attn);
        gemm_tf32_kernel<<<gC, 256>>>(p_attn, wproj + (size_t)l * CC * CC, p_h,
                                      BT, CC, CC, bproj + l * CC, p_h, 0);
        ln_kernel<<<BT, 256>>>(p_h, ln2s + l * CC, ln2b + l * CC, p_ain);
        gemm_tf32_kernel<<<gFF, 256>>>(p_ain, wff1 + (size_t)l * CC * FFD, p_ff,
                                       BT, FFD, CC, bff1 + l * FFD, nullptr, 1);
        gemm_tf32_kernel<<<gC, 256>>>(p_ff, wff2 + (size_t)l * FFD * CC, p_h,
                                      BT, CC, FFD, bff2 + l * CC, p_h, 0);
    }

    ln_kernel<<<BT, 256>>>(p_h, lnfs, lnfb, p_ain);
    gemm_tf32_kernel<<<gV, 256>>>(p_ain, lmw, out, BT, VV, CC, lmb, nullptr, 0);

    if ((long long)out_size > (long long)BT * VV) {
        zero_loss_kernel<<<1, 1>>>();
        loss_kernel<<<BT, 256>>>(out, target);
        finalize_loss_kernel<<<1, 1>>>(out);
    }
}

// round 4
// speedup vs baseline: 9.0026x; 1.5319x over previous
#include <cuda_runtime.h>
#include <math.h>
#include <stdint.h>

#define BATCH 2
#define TT    2048
#define BT    (BATCH*TT)          // 4096
#define CC    512
#define HH    8
#define HDIM  64
#define LLAY  4
#define VV    50257
#define VPAD  50304               // next multiple of 128
#define FFD   2048
#define LNEPS 1e-5f
#define BHZ   (BATCH*HH)          // 16

// ---------------- scratch (static device memory) -----------------------------
__device__ float g_h   [BT*CC];
__device__ float g_ain [BT*CC];
__device__ float g_qkv [BT*3*CC];
__device__ float g_attn[BT*CC];
__device__ float g_ff  [(size_t)BT*FFD];
__device__ float g_wqkv[(size_t)LLAY*CC*3*CC];
__device__ float g_wp  [(size_t)LLAY*CC*CC];
__device__ float g_w1  [(size_t)LLAY*CC*FFD];
__device__ float g_w2  [(size_t)LLAY*FFD*CC];
__device__ float g_lmw [(size_t)CC*VPAD];           // padded + pre-rounded LM weight
__device__ float g_scores[(size_t)BHZ*TT*TT];       // 268 MB score/prob buffer
__device__ float g_loss;

// ---------------- helpers ----------------------------------------------------
__device__ __forceinline__ float warpMax(float v) {
    #pragma unroll
    for (int o = 16; o; o >>= 1) v = fmaxf(v, __shfl_xor_sync(0xffffffffu, v, o));
    return v;
}
__device__ __forceinline__ float warpSum(float v) {
    #pragma unroll
    for (int o = 16; o; o >>= 1) v += __shfl_xor_sync(0xffffffffu, v, o);
    return v;
}
__device__ __forceinline__ float tf32r(float x) {
    uint32_t u;
    asm("cvt.rna.tf32.f32 %0, %1;" : "=r"(u) : "f"(x));
    return __uint_as_float(u);
}
__device__ __forceinline__ void mma8(float* c, const uint32_t* a, const uint32_t* b) {
    asm volatile(
        "mma.sync.aligned.m16n8k8.row.col.f32.tf32.tf32.f32 "
        "{%0,%1,%2,%3}, {%4,%5,%6,%7}, {%8,%9}, {%0,%1,%2,%3};"
        : "+f"(c[0]), "+f"(c[1]), "+f"(c[2]), "+f"(c[3])
        : "r"(a[0]), "r"(a[1]), "r"(a[2]), "r"(a[3]), "r"(b[0]), "r"(b[1]));
}
__device__ __forceinline__ uint32_t sptr(const void* p) {
    return (uint32_t)__cvta_generic_to_shared(p);
}
#define CP_ASYNC16(d, s) \
    asm volatile("cp.async.ca.shared.global [%0], [%1], 16;\n" :: "r"(d), "l"(s))
#define CP_COMMIT() asm volatile("cp.async.commit_group;\n" ::: "memory")
#define CP_WAIT1()  asm volatile("cp.async.wait_group 1;\n"  ::: "memory")
#define CP_WAIT0()  asm volatile("cp.async.wait_group 0;\n"  ::: "memory")

// ---------------- weight prep -------------------------------------------------
__global__ void pack_qkv_kernel(const float* __restrict__ wq,
                                const float* __restrict__ wk,
                                const float* __restrict__ wv) {
    int i = blockIdx.x * blockDim.x + threadIdx.x;
    const int total = LLAY * CC * 3 * CC;
    if (i >= total) return;
    int j = i % (3 * CC);
    int c = (i / (3 * CC)) % CC;
    int l = i / (3 * CC * CC);
    int which = j / CC;
    int jj = j % CC;
    int h = jj / HDIM, d = jj % HDIM;
    const float* w = (which == 0) ? wq : (which == 1) ? wk : wv;
    g_wqkv[i] = tf32r(w[(((size_t)l * HH + h) * CC + c) * HDIM + d]);
}

__global__ void roundcopy_kernel(float* __restrict__ dst,
                                 const float* __restrict__ src, int n) {
    int i = blockIdx.x * blockDim.x + threadIdx.x;
    if (i < n) dst[i] = tf32r(src[i]);
}

__global__ void pack_lmw_kernel(const float* __restrict__ lmw) {
    int i = blockIdx.x * blockDim.x + threadIdx.x;
    const int total = CC * VPAD;
    if (i >= total) return;
    int v = i % VPAD, c = i / VPAD;
    g_lmw[i] = (v < VV) ? tf32r(lmw[(size_t)c * VV + v]) : 0.f;
}

// ---------------- embedding ---------------------------------------------------
__global__ void embed_kernel(const int* __restrict__ x,
                             const float* __restrict__ tok,
                             const float* __restrict__ pos) {
    int i = blockIdx.x * blockDim.x + threadIdx.x;
    if (i >= BT * CC) return;
    int c  = i % CC;
    int bt = i / CC;
    int t  = bt % TT;
    g_h[i] = tok[(size_t)x[bt] * CC + c] + pos[(size_t)t * CC + c];
}

// ---------------- layernorm (outputs tf32-rounded: feeds GEMM A) -------------
__global__ void ln_kernel(const float* __restrict__ in,
                          const float* __restrict__ sc,
                          const float* __restrict__ bi,
                          float* __restrict__ out) {
    int row = blockIdx.x, tid = threadIdx.x;
    const float* r = in + (size_t)row * CC;
    float a = r[tid], b = r[tid + 256];
    float s = a + b, q = a * a + b * b;
    s = warpSum(s); q = warpSum(q);
    __shared__ float rs[8], rq[8];
    if ((tid & 31) == 0) { rs[tid >> 5] = s; rq[tid >> 5] = q; }
    __syncthreads();
    __shared__ float s_mean, s_rstd;
    if (tid == 0) {
        float S = 0.f, Q = 0.f;
        #pragma unroll
        for (int i = 0; i < 8; i++) { S += rs[i]; Q += rq[i]; }
        float m = S * (1.0f / CC);
        float v = Q * (1.0f / CC) - m * m;
        s_mean = m; s_rstd = rsqrtf(v + LNEPS);
    }
    __syncthreads();
    float m = s_mean, rstd = s_rstd;
    float* o = out + (size_t)row * CC;
    o[tid]       = tf32r((a - m) * rstd * sc[tid]       + bi[tid]);
    o[tid + 256] = tf32r((b - m) * rstd * sc[tid + 256] + bi[tid + 256]);
}

// ---------------- tf32 GEMM: C = A[M,K] @ B[K,ldB] ---------------------------
// 128x128 tile, BK=16, 256 threads (8 warps: 2x4, 64x32 each), cp.async 2-stage.
// A and B must be pre-rounded to tf32. M%128==0, K%16==0, B cols >= gridDim.x*128.
__global__ __launch_bounds__(256, 2)
void gemm_tf32_kernel(const float* __restrict__ A,
                      const float* __restrict__ B,
                      float* __restrict__ Cout,
                      int M, int N, int K, int ldB,
                      const float* __restrict__ bias,
                      const float* __restrict__ res,
                      int relu, int rndout) {
    __shared__ __align__(16) float As[2][128][20];
    __shared__ __align__(16) float Bs[2][16][136];
    int tid = threadIdx.x;
    int row0 = blockIdx.y * 128, col0 = blockIdx.x * 128;

    int lane = tid & 31, gid = lane >> 2, tig = lane & 3;
    int wid = tid >> 5;
    int wr = (wid >> 2) * 64;
    int wc = (wid & 3) * 32;

    float acc[4][4][4];
    #pragma unroll
    for (int i = 0; i < 4; i++)
        #pragma unroll
        for (int j = 0; j < 4; j++)
            #pragma unroll
            for (int q = 0; q < 4; q++) acc[i][j][q] = 0.f;

    // load coords (2 float4 each for A and B)
    int arr0 = (tid) >> 2,        akc0 = ((tid) & 3) << 2;
    int arr1 = (tid + 256) >> 2,  akc1 = ((tid + 256) & 3) << 2;
    int brr0 = (tid) >> 5,        bcc0 = ((tid) & 31) << 2;
    int brr1 = (tid + 256) >> 5,  bcc1 = ((tid + 256) & 31) << 2;

    #define LOAD_STAGE(st, k0)                                                   \
        do {                                                                     \
            CP_ASYNC16(sptr(&As[st][arr0][akc0]),                                \
                       A + (size_t)(row0 + arr0) * K + (k0) + akc0);             \
            CP_ASYNC16(sptr(&As[st][arr1][akc1]),                                \
                       A + (size_t)(row0 + arr1) * K + (k0) + akc1);             \
            CP_ASYNC16(sptr(&Bs[st][brr0][bcc0]),                                \
                       B + (size_t)((k0) + brr0) * ldB + col0 + bcc0);           \
            CP_ASYNC16(sptr(&Bs[st][brr1][bcc1]),                                \
                       B + (size_t)((k0) + brr1) * ldB + col0 + bcc1);           \
        } while (0)

    LOAD_STAGE(0, 0);
    CP_COMMIT();

    int ntiles = K >> 4;
    for (int it = 0; it < ntiles; it++) {
        int st = it & 1;
        if (it + 1 < ntiles) {
            LOAD_STAGE(st ^ 1, (it + 1) << 4);
            CP_COMMIT();
            CP_WAIT1();
        } else {
            CP_WAIT0();
        }
        __syncthreads();
        #pragma unroll
        for (int kb = 0; kb < 16; kb += 8) {
            uint32_t af[4][4], bf[4][2];
            #pragma unroll
            for (int i = 0; i < 4; i++) {
                int m = wr + i * 16 + gid;
                af[i][0] = __float_as_uint(As[st][m    ][kb + tig    ]);
                af[i][1] = __float_as_uint(As[st][m + 8][kb + tig    ]);
                af[i][2] = __float_as_uint(As[st][m    ][kb + tig + 4]);
                af[i][3] = __float_as_uint(As[st][m + 8][kb + tig + 4]);
            }
            #pragma unroll
            for (int j = 0; j < 4; j++) {
                int n = wc + j * 8 + gid;
                bf[j][0] = __float_as_uint(Bs[st][kb + tig    ][n]);
                bf[j][1] = __float_as_uint(Bs[st][kb + tig + 4][n]);
            }
            #pragma unroll
            for (int i = 0; i < 4; i++)
                #pragma unroll
                for (int j = 0; j < 4; j++)
                    mma8(acc[i][j], af[i], bf[j]);
        }
        __syncthreads();
    }
    #undef LOAD_STAGE

    #pragma unroll
    for (int i = 0; i < 4; i++)
        #pragma unroll
        for (int j = 0; j < 4; j++) {
            int c0 = col0 + wc + j * 8 + tig * 2;
            #pragma unroll
            for (int h2 = 0; h2 < 2; h2++) {
                int r = row0 + wr + i * 16 + gid + h2 * 8;
                float v0 = acc[i][j][h2 * 2 + 0];
                float v1 = acc[i][j][h2 * 2 + 1];
                if (c0 < N) {
                    if (bias) v0 += bias[c0];
                    if (res)  v0 += res[(size_t)r * N + c0];
                    if (relu) v0 = fmaxf(v0, 0.f);
                    if (rndout) v0 = tf32r(v0);
                    Cout[(size_t)r * N + c0] = v0;
                }
                if (c0 + 1 < N) {
                    if (bias) v1 += bias[c0 + 1];
                    if (res)  v1 += res[(size_t)r * N + c0 + 1];
                    if (relu) v1 = fmaxf(v1, 0.f);
                    if (rndout) v1 = tf32r(v1);
                    Cout[(size_t)r * N + c0 + 1] = v1;
                }
            }
        }
}

// ---------------- QK^T: scores[z][t][s] (causal-masked) ----------------------
__global__ void qk_kernel(const float* __restrict__ qkv,
                          float* __restrict__ scores) {
    __shared__ __align__(16) float Qs[64][72];   // [d][t]
    __shared__ __align__(16) float Ks[64][72];   // [d][s]
    int col0 = blockIdx.x * 64;    // s
    int row0 = blockIdx.y * 64;    // t
    if (col0 > row0 + 63) return;
    int z = blockIdx.z;
    int b = z >> 3, h = z & 7;
    const float* qbase = qkv + (size_t)b * TT * (3 * CC) + h * HDIM;
    const float* kbase = qbase + CC;
    int tid = threadIdx.x;

    #pragma unroll
    for (int i = 0; i < 4; i++) {
        int f4 = tid + i * 256;
        int r = f4 >> 4, kc = (f4 & 15) << 2;
        float4 q = *reinterpret_cast<const float4*>(
            qbase + (size_t)(row0 + r) * (3 * CC) + kc);
        float4 k = *reinterpret_cast<const float4*>(
            kbase + (size_t)(col0 + r) * (3 * CC) + kc);
        Qs[kc + 0][r] = q.x; Qs[kc + 1][r] = q.y;
        Qs[kc + 2][r] = q.z; Qs[kc + 3][r] = q.w;
        Ks[kc + 0][r] = k.x; Ks[kc + 1][r] = k.y;
        Ks[kc + 2][r] = k.z; Ks[kc + 3][r] = k.w;
    }
    __syncthreads();

    int lane = tid & 31, gid = lane >> 2, tig = lane & 3;
    int wid = tid >> 5;
    int wr = (wid >> 2) * 32, wc = (wid & 3) * 16;
    float acc[2][2][4] = {};

    #pragma unroll
    for (int ks = 0; ks < 8; ks++) {
        int kb = ks * 8;
        uint32_t a[2][4], bb[2][2];
        #pragma unroll
        for (int i = 0; i < 2; i++) {
            int m = wr + i * 16 + gid;
            a[i][0] = __float_as_uint(Qs[kb + tig    ][m    ]);
            a[i][1] = __float_as_uint(Qs[kb + tig    ][m + 8]);
            a[i][2] = __float_as_uint(Qs[kb + tig + 4][m    ]);
            a[i][3] = __float_as_uint(Qs[kb + tig + 4][m + 8]);
        }
        #pragma unroll
        for (int j = 0; j < 2; j++) {
            int n = wc + j * 8 + gid;
            bb[j][0] = __float_as_uint(Ks[kb + tig    ][n]);
            bb[j][1] = __float_as_uint(Ks[kb + tig + 4][n]);
        }
        #pragma unroll
        for (int i = 0; i < 2; i++)
            #pragma unroll
            for (int j = 0; j < 2; j++)
                mma8(acc[i][j], a[i], bb[j]);
    }

    #pragma unroll
    for (int i = 0; i < 2; i++)
        #pragma unroll
        for (int j = 0; j < 2; j++) {
            int s0 = col0 + wc + j * 8 + tig * 2;
            #pragma unroll
            for (int half = 0; half < 2; half++) {
                int t = row0 + wr + i * 16 + gid + half * 8;
                float v0 = acc[i][j][half * 2 + 0] * 0.125f;
                float v1 = acc[i][j][half * 2 + 1] * 0.125f;
                if (s0     > t) v0 = -1e30f;
                if (s0 + 1 > t) v1 = -1e30f;
                float* orow = scores + ((size_t)z * TT + t) * TT + s0;
                orow[0] = v0;
                orow[1] = v1;
            }
        }
}

// ---------------- softmax row (prefix [0..t]), outputs rounded ---------------
__global__ void softmax_kernel(float* __restrict__ scores) {
    __shared__ __align__(16) float scb[TT];
    __shared__ float red[8];
    int bx = blockIdx.x;
    int z = bx >> 11, t = bx & (TT - 1);
    float* row = scores + ((size_t)z * TT + t) * TT;
    int n = t + 1, tid = threadIdx.x;

    float mx = -1e30f;
    for (int i = tid; i < n; i += 256) { float v = row[i]; scb[i] = v; mx = fmaxf(mx, v); }
    mx = warpMax(mx);
    if ((tid & 31) == 0) red[tid >> 5] = mx;
    __syncthreads();
    float m = red[0];
    #pragma unroll
    for (int i = 1; i < 8; i++) m = fmaxf(m, red[i]);
    __syncthreads();

    float sm = 0.f;
    for (int i = tid; i < n; i += 256) { float e = __expf(scb[i] - m); scb[i] = e; sm += e; }
    sm = warpSum(sm);
    if ((tid & 31) == 0) red[tid >> 5] = sm;
    __syncthreads();
    float S = 0.f;
    #pragma unroll
    for (int i = 0; i < 8; i++) S += red[i];
    float inv = 1.f / S;

    for (int i4 = tid; i4 < TT / 4; i4 += 256) {
        int i = i4 * 4;
        float4 o;
        o.x = (i     < n) ? tf32r(scb[i    ] * inv) : 0.f;
        o.y = (i + 1 < n) ? tf32r(scb[i + 1] * inv) : 0.f;
        o.z = (i + 2 < n) ? tf32r(scb[i + 2] * inv) : 0.f;
        o.w = (i + 3 < n) ? tf32r(scb[i + 3] * inv) : 0.f;
        *reinterpret_cast<float4*>(row + i) = o;
    }
}

// ---------------- PV: attn[t][d] = sum_s P[t][s] V[s][d] ---------------------
__global__ void pv_kernel(const float* __restrict__ probs,
                          const float* __restrict__ qkv,
                          float* __restrict__ outp) {
    __shared__ __align__(16) float As[32][72];   // [s][t]
    __shared__ __align__(16) float Bs[32][72];   // [s][d]
    int row0 = blockIdx.x * 64;    // t tile
    int z = blockIdx.y;
    int b = z >> 3, h = z & 7;
    const float* pbase = probs + (size_t)z * TT * TT;
    const float* vbase = qkv + (size_t)b * TT * (3 * CC) + 2 * CC + h * HDIM;
    int tid = threadIdx.x;
    int lane = tid & 31, gid = lane >> 2, tig = lane & 3;
    int wid = tid >> 5;
    int wr = (wid >> 2) * 32, wc = (wid & 3) * 16;
    float acc[2][2][4] = {};

    int kend = row0 + 64;
    for (int k0 = 0; k0 < kend; k0 += 32) {
        #pragma unroll
        for (int i = 0; i < 2; i++) {
            int f4 = tid + i * 256;
            int r = f4 >> 3, kc = (f4 & 7) << 2;
            float4 v = *reinterpret_cast<const float4*>(
                pbase + (size_t)(row0 + r) * TT + k0 + kc);
            As[kc + 0][r] = v.x;
            As[kc + 1][r] = v.y;
            As[kc + 2][r] = v.z;
            As[kc + 3][r] = v.w;
        }
        #pragma unroll
        for (int i = 0; i < 2; i++) {
            int f4 = tid + i * 256;
            int r = f4 >> 4, c = (f4 & 15) << 2;
            float4 v = *reinterpret_cast<const float4*>(
                vbase + (size_t)(k0 + r) * (3 * CC) + c);
            Bs[r][c + 0] = v.x;
            Bs[r][c + 1] = v.y;
            Bs[r][c + 2] = v.z;
            Bs[r][c + 3] = v.w;
        }
        __syncthreads();
        #pragma unroll
        for (int ks = 0; ks < 4; ks++) {
            int kb = ks * 8;
            uint32_t a[2][4], bb[2][2];
            #pragma unroll
            for (int i = 0; i < 2; i++) {
                int m = wr + i * 16 + gid;
                a[i][0] = __float_as_uint(As[kb + tig    ][m    ]);
                a[i][1] = __float_as_uint(As[kb + tig    ][m + 8]);
                a[i][2] = __float_as_uint(As[kb + tig + 4][m    ]);
                a[i][3] = __float_as_uint(As[kb + tig + 4][m + 8]);
            }
            #pragma unroll
            for (int j = 0; j < 2; j++) {
                int n = wc + j * 8 + gid;
                bb[j][0] = __float_as_uint(Bs[kb + tig    ][n]);
                bb[j][1] = __float_as_uint(Bs[kb + tig + 4][n]);
            }
            #pragma unroll
            for (int i = 0; i < 2; i++)
                #pragma unroll
                for (int j = 0; j < 2; j++)
                    mma8(acc[i][j], a[i], bb[j]);
        }
        __syncthreads();
    }

    #pragma unroll
    for (int i = 0; i < 2; i++)
        #pragma unroll
        for (int j = 0; j < 2; j++) {
            int d0 = wc + j * 8 + tig * 2;
            #pragma unroll
            for (int half = 0; half < 2; half++) {
                int t = row0 + wr + i * 16 + gid + half * 8;
                float* op = outp + ((size_t)(b * TT + t)) * CC + h * HDIM + d0;
                op[0] = tf32r(acc[i][j][half * 2 + 0]);
                op[1] = tf32r(acc[i][j][half * 2 + 1]);
            }
        }
}

// ---------------- loss: single-pass online logsumexp (alignment-safe) --------
__global__ void zero_loss_kernel() { g_loss = 0.f; }

__global__ void loss_kernel(const float* __restrict__ logits,
                            const int* __restrict__ target) {
    int row = blockIdx.x, tid = threadIdx.x;
    const float* lr = logits + (size_t)row * VV;
    float m = -1e30f, s = 0.f;

    // prologue: scalar until lr+head is 16B-aligned (VV odd => varies per row)
    int head = (int)(((16u - ((uintptr_t)lr & 15u)) & 15u) >> 2);
    if (head > VV) head = VV;
    for (int i = tid; i < head; i += 256) {
        float v = lr[i];
        if (v > m) { s = s * __expf(m - v); m = v; }
        s += __expf(v - m);
    }
    // aligned float4 main body
    const float* lra = lr + head;
    int nrem = VV - head;
    int n4 = nrem >> 2;
    for (int i4 = tid; i4 < n4; i4 += 256) {
        float4 v = *reinterpret_cast<const float4*>(lra + i4 * 4);
        float vm = fmaxf(fmaxf(v.x, v.y), fmaxf(v.z, v.w));
        if (vm > m) { s = s * __expf(m - vm); m = vm; }
        s += __expf(v.x - m) + __expf(v.y - m) + __expf(v.z - m) + __expf(v.w - m);
    }
    // tail
    for (int i = head + n4 * 4 + tid; i < VV; i += 256) {
        float v = lr[i];
        if (v > m) { s = s * __expf(m - v); m = v; }
        s += __expf(v - m);
    }
    // pairwise (m,s) reduction within warp
    #pragma unroll
    for (int o = 16; o; o >>= 1) {
        float mo = __shfl_xor_sync(0xffffffffu, m, o);
        float so = __shfl_xor_sync(0xffffffffu, s, o);
        float M = fmaxf(m, mo);
        s = s * __expf(m - M) + so * __expf(mo - M);
        m = M;
    }
    __shared__ float rm[8], rs[8];
    if ((tid & 31) == 0) { rm[tid >> 5] = m; rs[tid >> 5] = s; }
    __syncthreads();
    if (tid == 0) {
        float M = rm[0];
        #pragma unroll
        for (int i = 1; i < 8; i++) M = fmaxf(M, rm[i]);
        float S = 0.f;
        #pragma unroll
        for (int i = 0; i < 8; i++) S += rs[i] * __expf(rm[i] - M);
        float lse = M + logf(S);
        atomicAdd(&g_loss, lse - lr[target[row]]);
    }
}

__global__ void finalize_loss_kernel(float* __restrict__ out) {
    out[(size_t)BT * VV] = g_loss * (1.0f / BT);
}

// ---------------- launch ------------------------------------------------------
extern "C" void kernel_launch(void* const* d_in, const int* in_sizes, int n_in,
                              void* d_out, int out_size) {
    const int*   x      = (const int*)  d_in[0];
    const int*   target = (const int*)  d_in[1];
    const float* tok    = (const float*)d_in[2];
    const float* pos    = (const float*)d_in[3];
    const float* ln1s   = (const float*)d_in[4];
    const float* ln1b   = (const float*)d_in[5];
    const float* wq     = (const float*)d_in[6];
    const float* wk     = (const float*)d_in[7];
    const float* wv     = (const float*)d_in[8];
    const float* wproj  = (const float*)d_in[9];
    const float* bproj  = (const float*)d_in[10];
    const float* ln2s   = (const float*)d_in[11];
    const float* ln2b   = (const float*)d_in[12];
    const float* wff1   = (const float*)d_in[13];
    const float* bff1   = (const float*)d_in[14];
    const float* wff2   = (const float*)d_in[15];
    const float* bff2   = (const float*)d_in[16];
    const float* lnfs   = (const float*)d_in[17];
    const float* lnfb   = (const float*)d_in[18];
    const float* lmw    = (const float*)d_in[19];
    const float* lmb    = (const float*)d_in[20];
    float* out = (float*)d_out;

    float *p_h, *p_ain, *p_qkv, *p_attn, *p_ff, *p_wqkv, *p_wp, *p_w1, *p_w2,
          *p_lmw, *p_sc;
    cudaGetSymbolAddress((void**)&p_h,    g_h);
    cudaGetSymbolAddress((void**)&p_ain,  g_ain);
    cudaGetSymbolAddress((void**)&p_qkv,  g_qkv);
    cudaGetSymbolAddress((void**)&p_attn, g_attn);
    cudaGetSymbolAddress((void**)&p_ff,   g_ff);
    cudaGetSymbolAddress((void**)&p_wqkv, g_wqkv);
    cudaGetSymbolAddress((void**)&p_wp,   g_wp);
    cudaGetSymbolAddress((void**)&p_w1,   g_w1);
    cudaGetSymbolAddress((void**)&p_w2,   g_w2);
    cudaGetSymbolAddress((void**)&p_lmw,  g_lmw);
    cudaGetSymbolAddress((void**)&p_sc,   g_scores);

    // weight prep
    const int packN = LLAY * CC * 3 * CC;
    pack_qkv_kernel<<<(packN + 255) / 256, 256>>>(wq, wk, wv);
    {
        int n = LLAY * CC * CC;
        roundcopy_kernel<<<(n + 255) / 256, 256>>>(p_wp, wproj, n);
        n = LLAY * CC * FFD;
        roundcopy_kernel<<<(n + 255) / 256, 256>>>(p_w1, wff1, n);
        n = LLAY * FFD * CC;
        roundcopy_kernel<<<(n + 255) / 256, 256>>>(p_w2, wff2, n);
        int nl = CC * VPAD;
        pack_lmw_kernel<<<(nl + 255) / 256, 256>>>(lmw);
    }
    embed_kernel<<<(BT * CC + 255) / 256, 256>>>(x, tok, pos);

    dim3 gQKV((3 * CC) / 128, BT / 128);
    dim3 gC  (CC / 128,       BT / 128);
    dim3 gFF (FFD / 128,      BT / 128);
    dim3 gV  (VPAD / 128,     BT / 128);
    dim3 gQK (TT / 64, TT / 64, BHZ);
    dim3 gPV (TT / 64, BHZ);

    for (int l = 0; l < LLAY; l++) {
        ln_kernel<<<BT, 256>>>(p_h, ln1s + l * CC, ln1b + l * CC, p_ain);
        gemm_tf32_kernel<<<gQKV, 256>>>(p_ain, p_wqkv + (size_t)l * CC * 3 * CC,
                                        p_qkv, BT, 3 * CC, CC, 3 * CC,
                                        nullptr, nullptr, 0, 1);
        qk_kernel<<<gQK, 256>>>(p_qkv, p_sc);
        softmax_kernel<<<BHZ * TT, 256>>>(p_sc);
        pv_kernel<<<gPV, 256>>>(p_sc, p_qkv, p_attn);
        gemm_tf32_kernel<<<gC, 256>>>(p_attn, p_wp + (size_t)l * CC * CC, p_h,
                                      BT, CC, CC, CC, bproj + l * CC, p_h, 0, 0);
        ln_kernel<<<BT, 256>>>(p_h, ln2s + l * CC, ln2b + l * CC, p_ain);
        gemm_tf32_kernel<<<gFF, 256>>>(p_ain, p_w1 + (size_t)l * CC * FFD, p_ff,
                                       BT, FFD, CC, FFD, bff1 + l * FFD,
                                       nullptr, 1, 1);
        gemm_tf32_kernel<<<gC, 256>>>(p_ff, p_w2 + (size_t)l * FFD * CC, p_h,
                                      BT, CC, FFD, CC, bff2 + l * CC, p_h, 0, 0);
    }

    ln_kernel<<<BT, 256>>>(p_h, lnfs, lnfb, p_ain);
    gemm_tf32_kernel<<<gV, 256>>>(p_ain, p_lmw, out, BT, VV, CC, VPAD,
                                  lmb, nullptr, 0, 0);

    if ((long long)out_size > (long long)BT * VV) {
        zero_loss_kernel<<<1, 1>>>();
        loss_kernel<<<BT, 256>>>(out, target);
        finalize_loss_kernel<<<1, 1>>>(out);
    }
}

// round 5
// speedup vs baseline: 11.5638x; 1.2845x over previous
#include <cuda_runtime.h>
#include <math.h>
#include <stdint.h>

#define BATCH 2
#define TT    2048
#define BT    (BATCH*TT)          // 4096
#define CC    512
#define HH    8
#define HDIM  64
#define LLAY  4
#define VV    50257
#define VPAD  50304               // next multiple of 128
#define FFD   2048
#define LNEPS 1e-5f
#define BHZ   (BATCH*HH)          // 16

// ---------------- scratch (static device memory) -----------------------------
__device__ float g_h   [BT*CC];
__device__ float g_ain [BT*CC];
__device__ float g_qkv [BT*3*CC];
__device__ float g_attn[BT*CC];
__device__ float g_ff  [(size_t)BT*FFD];
__device__ float g_wqkv[(size_t)LLAY*CC*3*CC];
__device__ float g_wp  [(size_t)LLAY*CC*CC];
__device__ float g_w1  [(size_t)LLAY*CC*FFD];
__device__ float g_w2  [(size_t)LLAY*FFD*CC];
__device__ float g_lmw [(size_t)CC*VPAD];           // padded + pre-rounded LM weight
__device__ float g_loss;

// ---------------- helpers ----------------------------------------------------
__device__ __forceinline__ float warpSum(float v) {
    #pragma unroll
    for (int o = 16; o; o >>= 1) v += __shfl_xor_sync(0xffffffffu, v, o);
    return v;
}
__device__ __forceinline__ float tf32r(float x) {
    uint32_t u;
    asm("cvt.rna.tf32.f32 %0, %1;" : "=r"(u) : "f"(x));
    return __uint_as_float(u);
}
__device__ __forceinline__ void mma8(float* c, const uint32_t* a, const uint32_t* b) {
    asm volatile(
        "mma.sync.aligned.m16n8k8.row.col.f32.tf32.tf32.f32 "
        "{%0,%1,%2,%3}, {%4,%5,%6,%7}, {%8,%9}, {%0,%1,%2,%3};"
        : "+f"(c[0]), "+f"(c[1]), "+f"(c[2]), "+f"(c[3])
        : "r"(a[0]), "r"(a[1]), "r"(a[2]), "r"(a[3]), "r"(b[0]), "r"(b[1]));
}
__device__ __forceinline__ uint32_t sptr(const void* p) {
    return (uint32_t)__cvta_generic_to_shared(p);
}
#define CP_ASYNC16(d, s) \
    asm volatile("cp.async.ca.shared.global [%0], [%1], 16;\n" :: "r"(d), "l"(s))
#define CP_COMMIT() asm volatile("cp.async.commit_group;\n" ::: "memory")
#define CP_WAIT1()  asm volatile("cp.async.wait_group 1;\n"  ::: "memory")
#define CP_WAIT0()  asm volatile("cp.async.wait_group 0;\n"  ::: "memory")

// ---------------- weight prep -------------------------------------------------
__global__ void pack_qkv_kernel(const float* __restrict__ wq,
                                const float* __restrict__ wk,
                                const float* __restrict__ wv) {
    int i = blockIdx.x * blockDim.x + threadIdx.x;
    const int total = LLAY * CC * 3 * CC;
    if (i >= total) return;
    int j = i % (3 * CC);
    int c = (i / (3 * CC)) % CC;
    int l = i / (3 * CC * CC);
    int which = j / CC;
    int jj = j % CC;
    int h = jj / HDIM, d = jj % HDIM;
    const float* w = (which == 0) ? wq : (which == 1) ? wk : wv;
    g_wqkv[i] = tf32r(w[(((size_t)l * HH + h) * CC + c) * HDIM + d]);
}

__global__ void roundcopy_kernel(float* __restrict__ dst,
                                 const float* __restrict__ src, int n) {
    int i = blockIdx.x * blockDim.x + threadIdx.x;
    if (i < n) dst[i] = tf32r(src[i]);
}

__global__ void pack_lmw_kernel(const float* __restrict__ lmw) {
    int i = blockIdx.x * blockDim.x + threadIdx.x;
    const int total = CC * VPAD;
    if (i >= total) return;
    int v = i % VPAD, c = i / VPAD;
    g_lmw[i] = (v < VV) ? tf32r(lmw[(size_t)c * VV + v]) : 0.f;
}

// ---------------- embedding ---------------------------------------------------
__global__ void embed_kernel(const int* __restrict__ x,
                             const float* __restrict__ tok,
                             const float* __restrict__ pos) {
    int i = blockIdx.x * blockDim.x + threadIdx.x;
    if (i >= BT * CC) return;
    int c  = i % CC;
    int bt = i / CC;
    int t  = bt % TT;
    g_h[i] = tok[(size_t)x[bt] * CC + c] + pos[(size_t)t * CC + c];
}

// ---------------- layernorm (outputs tf32-rounded: feeds GEMM A) -------------
__global__ void ln_kernel(const float* __restrict__ in,
                          const float* __restrict__ sc,
                          const float* __restrict__ bi,
                          float* __restrict__ out) {
    int row = blockIdx.x, tid = threadIdx.x;
    const float* r = in + (size_t)row * CC;
    float a = r[tid], b = r[tid + 256];
    float s = a + b, q = a * a + b * b;
    s = warpSum(s); q = warpSum(q);
    __shared__ float rs[8], rq[8];
    if ((tid & 31) == 0) { rs[tid >> 5] = s; rq[tid >> 5] = q; }
    __syncthreads();
    __shared__ float s_mean, s_rstd;
    if (tid == 0) {
        float S = 0.f, Q = 0.f;
        #pragma unroll
        for (int i = 0; i < 8; i++) { S += rs[i]; Q += rq[i]; }
        float m = S * (1.0f / CC);
        float v = Q * (1.0f / CC) - m * m;
        s_mean = m; s_rstd = rsqrtf(v + LNEPS);
    }
    __syncthreads();
    float m = s_mean, rstd = s_rstd;
    float* o = out + (size_t)row * CC;
    o[tid]       = tf32r((a - m) * rstd * sc[tid]       + bi[tid]);
    o[tid + 256] = tf32r((b - m) * rstd * sc[tid + 256] + bi[tid + 256]);
}

// ---------------- tf32 GEMM: C = A[M,K] @ B[K,ldB] ---------------------------
__global__ __launch_bounds__(256, 2)
void gemm_tf32_kernel(const float* __restrict__ A,
                      const float* __restrict__ B,
                      float* __restrict__ Cout,
                      int M, int N, int K, int ldB,
                      const float* __restrict__ bias,
                      const float* __restrict__ res,
                      int relu, int rndout) {
    __shared__ __align__(16) float As[2][128][20];
    __shared__ __align__(16) float Bs[2][16][136];
    int tid = threadIdx.x;
    int row0 = blockIdx.y * 128, col0 = blockIdx.x * 128;

    int lane = tid & 31, gid = lane >> 2, tig = lane & 3;
    int wid = tid >> 5;
    int wr = (wid >> 2) * 64;
    int wc = (wid & 3) * 32;

    float acc[4][4][4];
    #pragma unroll
    for (int i = 0; i < 4; i++)
        #pragma unroll
        for (int j = 0; j < 4; j++)
            #pragma unroll
            for (int q = 0; q < 4; q++) acc[i][j][q] = 0.f;

    int arr0 = (tid) >> 2,        akc0 = ((tid) & 3) << 2;
    int arr1 = (tid + 256) >> 2,  akc1 = ((tid + 256) & 3) << 2;
    int brr0 = (tid) >> 5,        bcc0 = ((tid) & 31) << 2;
    int brr1 = (tid + 256) >> 5,  bcc1 = ((tid + 256) & 31) << 2;

    #define LOAD_STAGE(st, k0)                                                   \
        do {                                                                     \
            CP_ASYNC16(sptr(&As[st][arr0][akc0]),                                \
                       A + (size_t)(row0 + arr0) * K + (k0) + akc0);             \
            CP_ASYNC16(sptr(&As[st][arr1][akc1]),                                \
                       A + (size_t)(row0 + arr1) * K + (k0) + akc1);             \
            CP_ASYNC16(sptr(&Bs[st][brr0][bcc0]),                                \
                       B + (size_t)((k0) + brr0) * ldB + col0 + bcc0);           \
            CP_ASYNC16(sptr(&Bs[st][brr1][bcc1]),                                \
                       B + (size_t)((k0) + brr1) * ldB + col0 + bcc1);           \
        } while (0)

    LOAD_STAGE(0, 0);
    CP_COMMIT();

    int ntiles = K >> 4;
    for (int it = 0; it < ntiles; it++) {
        int st = it & 1;
        if (it + 1 < ntiles) {
            LOAD_STAGE(st ^ 1, (it + 1) << 4);
            CP_COMMIT();
            CP_WAIT1();
        } else {
            CP_WAIT0();
        }
        __syncthreads();
        #pragma unroll
        for (int kb = 0; kb < 16; kb += 8) {
            uint32_t af[4][4], bf[4][2];
            #pragma unroll
            for (int i = 0; i < 4; i++) {
                int m = wr + i * 16 + gid;
                af[i][0] = __float_as_uint(As[st][m    ][kb + tig    ]);
                af[i][1] = __float_as_uint(As[st][m + 8][kb + tig    ]);
                af[i][2] = __float_as_uint(As[st][m    ][kb + tig + 4]);
                af[i][3] = __float_as_uint(As[st][m + 8][kb + tig + 4]);
            }
            #pragma unroll
            for (int j = 0; j < 4; j++) {
                int n = wc + j * 8 + gid;
                bf[j][0] = __float_as_uint(Bs[st][kb + tig    ][n]);
                bf[j][1] = __float_as_uint(Bs[st][kb + tig + 4][n]);
            }
            #pragma unroll
            for (int i = 0; i < 4; i++)
                #pragma unroll
                for (int j = 0; j < 4; j++)
                    mma8(acc[i][j], af[i], bf[j]);
        }
        __syncthreads();
    }
    #undef LOAD_STAGE

    #pragma unroll
    for (int i = 0; i < 4; i++)
        #pragma unroll
        for (int j = 0; j < 4; j++) {
            int c0 = col0 + wc + j * 8 + tig * 2;
            #pragma unroll
            for (int h2 = 0; h2 < 2; h2++) {
                int r = row0 + wr + i * 16 + gid + h2 * 8;
                float v0 = acc[i][j][h2 * 2 + 0];
                float v1 = acc[i][j][h2 * 2 + 1];
                if (c0 < N) {
                    if (bias) v0 += bias[c0];
                    if (res)  v0 += res[(size_t)r * N + c0];
                    if (relu) v0 = fmaxf(v0, 0.f);
                    if (rndout) v0 = tf32r(v0);
                    Cout[(size_t)r * N + c0] = v0;
                }
                if (c0 + 1 < N) {
                    if (bias) v1 += bias[c0 + 1];
                    if (res)  v1 += res[(size_t)r * N + c0 + 1];
                    if (relu) v1 = fmaxf(v1, 0.f);
                    if (rndout) v1 = tf32r(v1);
                    Cout[(size_t)r * N + c0 + 1] = v1;
                }
            }
        }
}

// ---------------- fused flash attention --------------------------------------
// Block: 128 q-rows x one (b,h). 8 warps, each warp owns 16 q-rows x all 64 s.
// Online softmax stats fully warp-local. K/V staged per 64-s tile; P via
// warp-private smem columns (no cross-warp dependency on Ps).
#define FBQ 128
#define FBS 64
#define KLD 68
#define VLD 72
#define PLD 136
#define FSMEM ((FBS*KLD + FBS*VLD + FBS*PLD) * 4)   // 70656 bytes

__global__ __launch_bounds__(256, 1)
void flash_kernel(const float* __restrict__ qkv, float* __restrict__ outp) {
    extern __shared__ float fsm[];
    float* Ks = fsm;                       // [s][KLD]
    float* Vs = fsm + FBS * KLD;           // [s][VLD]
    float* Ps = fsm + FBS * (KLD + VLD);   // [s][PLD]

    int tid = threadIdx.x;
    int lane = tid & 31, gid = lane >> 2, tig = lane & 3;
    int wid = tid >> 5;
    int wrow = wid * 16;
    int q0 = blockIdx.x * FBQ;
    int z = blockIdx.y;
    int b = z >> 3, h = z & 7;
    const float* qbase = qkv + (size_t)b * TT * (3 * CC) + h * HDIM;
    const float* kbase = qbase + CC;
    const float* vbase = qbase + 2 * CC;

    // Q fragments in registers (values already tf32-rounded)
    uint32_t aQ[8][4];
    {
        int t0 = q0 + wrow + gid;
        const float* q0p = qbase + (size_t)t0 * (3 * CC);
        const float* q1p = q0p + 8 * (3 * CC);
        #pragma unroll
        for (int ks = 0; ks < 8; ks++) {
            aQ[ks][0] = __float_as_uint(q0p[ks * 8 + tig]);
            aQ[ks][1] = __float_as_uint(q1p[ks * 8 + tig]);
            aQ[ks][2] = __float_as_uint(q0p[ks * 8 + tig + 4]);
            aQ[ks][3] = __float_as_uint(q1p[ks * 8 + tig + 4]);
        }
    }

    float oAcc[8][4];
    #pragma unroll
    for (int j = 0; j < 8; j++)
        #pragma unroll
        for (int q = 0; q < 4; q++) oAcc[j][q] = 0.f;
    float m0 = -1e30f, m1 = -1e30f, l0 = 0.f, l1 = 0.f;

    int t0g = q0 + wrow + gid, t1g = t0g + 8;
    int nTiles = q0 / FBS + 2;

    for (int it = 0; it < nTiles; it++) {
        int s0 = it * FBS;
        __syncthreads();   // prior PV reads of Ks/Vs complete
        // load K,V tiles [64 x 64], row-major, coalesced, conflict-free stores
        #pragma unroll
        for (int i = 0; i < 4; i++) {
            int f4 = tid + i * 256;
            int r = f4 >> 4, kc = (f4 & 15) << 2;
            float4 kv = *reinterpret_cast<const float4*>(
                kbase + (size_t)(s0 + r) * (3 * CC) + kc);
            *reinterpret_cast<float4*>(Ks + r * KLD + kc) = kv;
            float4 vv = *reinterpret_cast<const float4*>(
                vbase + (size_t)(s0 + r) * (3 * CC) + kc);
            *reinterpret_cast<float4*>(Vs + r * VLD + kc) = vv;
        }
        __syncthreads();

        // S = Q K^T for this warp's 16 rows x 64 cols
        float sAcc[8][4];
        #pragma unroll
        for (int j = 0; j < 8; j++)
            #pragma unroll
            for (int q = 0; q < 4; q++) sAcc[j][q] = 0.f;
        #pragma unroll
        for (int ks = 0; ks < 8; ks++) {
            int kb = ks * 8;
            #pragma unroll
            for (int j = 0; j < 8; j++) {
                int n = j * 8 + gid;
                uint32_t bb[2];
                bb[0] = __float_as_uint(Ks[n * KLD + kb + tig]);
                bb[1] = __float_as_uint(Ks[n * KLD + kb + tig + 4]);
                mma8(sAcc[j], aQ[ks], bb);
            }
        }

        // scale + causal mask
        #pragma unroll
        for (int j = 0; j < 8; j++) {
            int sb = s0 + j * 8 + tig * 2;
            #pragma unroll
            for (int q = 0; q < 4; q++) {
                float v = sAcc[j][q] * 0.125f;
                int s_g = sb + (q & 1);
                int t_g = (q < 2) ? t0g : t1g;
                sAcc[j][q] = (s_g > t_g) ? -1e30f : v;
            }
        }

        // row max (warp-local: reduce over j then tig lanes)
        float rm0 = -1e30f, rm1 = -1e30f;
        #pragma unroll
        for (int j = 0; j < 8; j++) {
            rm0 = fmaxf(rm0, fmaxf(sAcc[j][0], sAcc[j][1]));
            rm1 = fmaxf(rm1, fmaxf(sAcc[j][2], sAcc[j][3]));
        }
        #pragma unroll
        for (int o = 1; o <= 2; o <<= 1) {
            rm0 = fmaxf(rm0, __shfl_xor_sync(0xffffffffu, rm0, o));
            rm1 = fmaxf(rm1, __shfl_xor_sync(0xffffffffu, rm1, o));
        }
        float nm0 = fmaxf(m0, rm0), nm1 = fmaxf(m1, rm1);
        float a0 = __expf(m0 - nm0), a1 = __expf(m1 - nm1);

        // p = exp(s - m), store rounded to Ps (warp-private columns), row sums
        float rs0 = 0.f, rs1 = 0.f;
        #pragma unroll
        for (int j = 0; j < 8; j++) {
            int sb = (j * 8 + tig * 2) * PLD;
            float p0 = __expf(sAcc[j][0] - nm0);
            float p1 = __expf(sAcc[j][1] - nm0);
            float p2 = __expf(sAcc[j][2] - nm1);
            float p3 = __expf(sAcc[j][3] - nm1);
            rs0 += p0 + p1; rs1 += p2 + p3;
            int tc0 = wrow + gid, tc1 = tc0 + 8;
            Ps[sb       + tc0] = tf32r(p0);
            Ps[sb + PLD + tc0] = tf32r(p1);
            Ps[sb       + tc1] = tf32r(p2);
            Ps[sb + PLD + tc1] = tf32r(p3);
        }
        #pragma unroll
        for (int o = 1; o <= 2; o <<= 1) {
            rs0 += __shfl_xor_sync(0xffffffffu, rs0, o);
            rs1 += __shfl_xor_sync(0xffffffffu, rs1, o);
        }
        l0 = l0 * a0 + rs0;
        l1 = l1 * a1 + rs1;
        m0 = nm0; m1 = nm1;

        // rescale O accumulators
        #pragma unroll
        for (int j = 0; j < 8; j++) {
            oAcc[j][0] *= a0; oAcc[j][1] *= a0;
            oAcc[j][2] *= a1; oAcc[j][3] *= a1;
        }
        __syncwarp();

        // O += P V (A from warp-own Ps columns, B from Vs)
        #pragma unroll
        for (int ks = 0; ks < 8; ks++) {
            int kb = ks * 8;
            uint32_t aP[4];
            int mr = wrow + gid;
            aP[0] = __float_as_uint(Ps[(kb + tig    ) * PLD + mr    ]);
            aP[1] = __float_as_uint(Ps[(kb + tig    ) * PLD + mr + 8]);
            aP[2] = __float_as_uint(Ps[(kb + tig + 4) * PLD + mr    ]);
            aP[3] = __float_as_uint(Ps[(kb + tig + 4) * PLD + mr + 8]);
            #pragma unroll
            for (int j = 0; j < 8; j++) {
                int n = j * 8 + gid;
                uint32_t bb[2];
                bb[0] = __float_as_uint(Vs[(kb + tig    ) * VLD + n]);
                bb[1] = __float_as_uint(Vs[(kb + tig + 4) * VLD + n]);
                mma8(oAcc[j], aP, bb);
            }
        }
    }

    // finalize: divide by l, round, write
    float inv0 = 1.f / l0, inv1 = 1.f / l1;
    float* o0 = outp + (size_t)(b * TT + t0g) * CC + h * HDIM;
    float* o1 = outp + (size_t)(b * TT + t1g) * CC + h * HDIM;
    #pragma unroll
    for (int j = 0; j < 8; j++) {
        int d = j * 8 + tig * 2;
        o0[d]     = tf32r(oAcc[j][0] * inv0);
        o0[d + 1] = tf32r(oAcc[j][1] * inv0);
        o1[d]     = tf32r(oAcc[j][2] * inv1);
        o1[d + 1] = tf32r(oAcc[j][3] * inv1);
    }
}

// ---------------- loss: single-pass online logsumexp (alignment-safe) --------
__global__ void zero_loss_kernel() { g_loss = 0.f; }

__global__ void loss_kernel(const float* __restrict__ logits,
                            const int* __restrict__ target) {
    int row = blockIdx.x, tid = threadIdx.x;
    const float* lr = logits + (size_t)row * VV;
    float m = -1e30f, s = 0.f;

    int head = (int)(((16u - ((uintptr_t)lr & 15u)) & 15u) >> 2);
    if (head > VV) head = VV;
    for (int i = tid; i < head; i += 256) {
        float v = lr[i];
        if (v > m) { s = s * __expf(m - v); m = v; }
        s += __expf(v - m);
    }
    const float* lra = lr + head;
    int nrem = VV - head;
    int n4 = nrem >> 2;
    for (int i4 = tid; i4 < n4; i4 += 256) {
        float4 v = *reinterpret_cast<const float4*>(lra + i4 * 4);
        float vm = fmaxf(fmaxf(v.x, v.y), fmaxf(v.z, v.w));
        if (vm > m) { s = s * __expf(m - vm); m = vm; }
        s += __expf(v.x - m) + __expf(v.y - m) + __expf(v.z - m) + __expf(v.w - m);
    }
    for (int i = head + n4 * 4 + tid; i < VV; i += 256) {
        float v = lr[i];
        if (v > m) { s = s * __expf(m - v); m = v; }
        s += __expf(v - m);
    }
    #pragma unroll
    for (int o = 16; o; o >>= 1) {
        float mo = __shfl_xor_sync(0xffffffffu, m, o);
        float so = __shfl_xor_sync(0xffffffffu, s, o);
        float M = fmaxf(m, mo);
        s = s * __expf(m - M) + so * __expf(mo - M);
        m = M;
    }
    __shared__ float rm[8], rs[8];
    if ((tid & 31) == 0) { rm[tid >> 5] = m; rs[tid >> 5] = s; }
    __syncthreads();
    if (tid == 0) {
        float M = rm[0];
        #pragma unroll
        for (int i = 1; i < 8; i++) M = fmaxf(M, rm[i]);
        float S = 0.f;
        #pragma unroll
        for (int i = 0; i < 8; i++) S += rs[i] * __expf(rm[i] - M);
        float lse = M + logf(S);
        atomicAdd(&g_loss, lse - lr[target[row]]);
    }
}

__global__ void finalize_loss_kernel(float* __restrict__ out) {
    out[(size_t)BT * VV] = g_loss * (1.0f / BT);
}

// ---------------- launch ------------------------------------------------------
extern "C" void kernel_launch(void* const* d_in, const int* in_sizes, int n_in,
                              void* d_out, int out_size) {
    const int*   x      = (const int*)  d_in[0];
    const int*   target = (const int*)  d_in[1];
    const float* tok    = (const float*)d_in[2];
    const float* pos    = (const float*)d_in[3];
    const float* ln1s   = (const float*)d_in[4];
    const float* ln1b   = (const float*)d_in[5];
    const float* wq     = (const float*)d_in[6];
    const float* wk     = (const float*)d_in[7];
    const float* wv     = (const float*)d_in[8];
    const float* wproj  = (const float*)d_in[9];
    const float* bproj  = (const float*)d_in[10];
    const float* ln2s   = (const float*)d_in[11];
    const float* ln2b   = (const float*)d_in[12];
    const float* wff1   = (const float*)d_in[13];
    const float* bff1   = (const float*)d_in[14];
    const float* wff2   = (const float*)d_in[15];
    const float* bff2   = (const float*)d_in[16];
    const float* lnfs   = (const float*)d_in[17];
    const float* lnfb   = (const float*)d_in[18];
    const float* lmw    = (const float*)d_in[19];
    const float* lmb    = (const float*)d_in[20];
    float* out = (float*)d_out;

    float *p_h, *p_ain, *p_qkv, *p_attn, *p_ff, *p_wqkv, *p_wp, *p_w1, *p_w2,
          *p_lmw;
    cudaGetSymbolAddress((void**)&p_h,    g_h);
    cudaGetSymbolAddress((void**)&p_ain,  g_ain);
    cudaGetSymbolAddress((void**)&p_qkv,  g_qkv);
    cudaGetSymbolAddress((void**)&p_attn, g_attn);
    cudaGetSymbolAddress((void**)&p_ff,   g_ff);
    cudaGetSymbolAddress((void**)&p_wqkv, g_wqkv);
    cudaGetSymbolAddress((void**)&p_wp,   g_wp);
    cudaGetSymbolAddress((void**)&p_w1,   g_w1);
    cudaGetSymbolAddress((void**)&p_w2,   g_w2);
    cudaGetSymbolAddress((void**)&p_lmw,  g_lmw);

    static int attr_done = 0;
    if (!attr_done) {
        cudaFuncSetAttribute(flash_kernel,
                             cudaFuncAttributeMaxDynamicSharedMemorySize, FSMEM);
        attr_done = 1;
    }

    // weight prep
    const int packN = LLAY * CC * 3 * CC;
    pack_qkv_kernel<<<(packN + 255) / 256, 256>>>(wq, wk, wv);
    {
        int n = LLAY * CC * CC;
        roundcopy_kernel<<<(n + 255) / 256, 256>>>(p_wp, wproj, n);
        n = LLAY * CC * FFD;
        roundcopy_kernel<<<(n + 255) / 256, 256>>>(p_w1, wff1, n);
        n = LLAY * FFD * CC;
        roundcopy_kernel<<<(n + 255) / 256, 256>>>(p_w2, wff2, n);
        int nl = CC * VPAD;
        pack_lmw_kernel<<<(nl + 255) / 256, 256>>>(lmw);
    }
    embed_kernel<<<(BT * CC + 255) / 256, 256>>>(x, tok, pos);

    dim3 gQKV((3 * CC) / 128, BT / 128);
    dim3 gC  (CC / 128,       BT / 128);
    dim3 gFF (FFD / 128,      BT / 128);
    dim3 gV  (VPAD / 128,     BT / 128);
    dim3 gFA (TT / FBQ, BHZ);

    for (int l = 0; l < LLAY; l++) {
        ln_kernel<<<BT, 256>>>(p_h, ln1s + l * CC, ln1b + l * CC, p_ain);
        gemm_tf32_kernel<<<gQKV, 256>>>(p_ain, p_wqkv + (size_t)l * CC * 3 * CC,
                                        p_qkv, BT, 3 * CC, CC, 3 * CC,
                                        nullptr, nullptr, 0, 1);
        flash_kernel<<<gFA, 256, FSMEM>>>(p_qkv, p_attn);
        gemm_tf32_kernel<<<gC, 256>>>(p_attn, p_wp + (size_t)l * CC * CC, p_h,
                                      BT, CC, CC, CC, bproj + l * CC, p_h, 0, 0);
        ln_kernel<<<BT, 256>>>(p_h, ln2s + l * CC, ln2b + l * CC, p_ain);
        gemm_tf32_kernel<<<gFF, 256>>>(p_ain, p_w1 + (size_t)l * CC * FFD, p_ff,
                                       BT, FFD, CC, FFD, bff1 + l * FFD,
                                       nullptr, 1, 1);
        gemm_tf32_kernel<<<gC, 256>>>(p_ff, p_w2 + (size_t)l * FFD * CC, p_h,
                                      BT, CC, FFD, CC, bff2 + l * CC, p_h, 0, 0);
    }

    ln_kernel<<<BT, 256>>>(p_h, lnfs, lnfb, p_ain);
    gemm_tf32_kernel<<<gV, 256>>>(p_ain, p_lmw, out, BT, VV, CC, VPAD,
                                  lmb, nullptr, 0, 0);

    if ((long long)out_size > (long long)BT * VV) {
        zero_loss_kernel<<<1, 1>>>();
        loss_kernel<<<BT, 256>>>(out, target);
        finalize_loss_kernel<<<1, 1>>>(out);
    }
}